// round 2
// baseline (speedup 1.0000x reference)
#include <cuda_runtime.h>

// N-step discounted return, T=1024, B=4096, horizon=16, gamma=0.99.
// g[t,b] = sum_{h=0..15, t+h<T} g^h * r[t+h,b]*m[t+h,b]
//        + g^{min(t+16,T)-t} * V[min(t+15,T-1), b]
//
// Strategy: one thread per (column b, time-chunk). Register ring buffer of the
// 16-wide rm window; backward sliding-window recurrence
//   S(t) = rm[t] + g*S(t+1) - g^16 * rm[t+16]
// so each rm element is loaded ~(1 + 15/CH) times instead of 16 times.

#define TT 1024
#define BB 4096
#define HORIZON 16
#define CH 32           // time rows per thread

constexpr float GAMMA = 0.99f;

__host__ __device__ constexpr float gpow(int n) {
    float x = 1.0f;
    for (int i = 0; i < n; ++i) x *= GAMMA;
    return x;
}

__device__ __constant__ float GP[17] = {
    gpow(0),  gpow(1),  gpow(2),  gpow(3),  gpow(4),  gpow(5),
    gpow(6),  gpow(7),  gpow(8),  gpow(9),  gpow(10), gpow(11),
    gpow(12), gpow(13), gpow(14), gpow(15), gpow(16)
};

__global__ __launch_bounds__(256)
void nstep_return_kernel(const float* __restrict__ rew,
                         const float* __restrict__ val,
                         const float* __restrict__ msk,
                         float* __restrict__ out)
{
    const int b  = blockIdx.x * 256 + threadIdx.x;   // column
    const int t1 = blockIdx.y * CH + CH;             // chunk end (TT % CH == 0)

    constexpr float G16 = gpow(16);

    // Ring buffer w[(t+i) & 15] = rm[t+i] for the current window [t, t+15].
    float w[HORIZON];
    float S = 0.0f;

    // Init window at t = t1-1: rm[t1-1 .. t1+14], Horner for S.
#pragma unroll
    for (int i = HORIZON - 1; i >= 0; --i) {
        const int tt = t1 - 1 + i;
        float x = 0.0f;
        if (tt < TT) x = rew[tt * BB + b] * msk[tt * BB + b];
        w[tt & (HORIZON - 1)] = x;
        S = fmaf(S, GAMMA, x);          // S = x + GAMMA*S
    }

    // Backward over the chunk.
#pragma unroll
    for (int j = 0; j < CH; ++j) {
        const int t = t1 - 1 - j;

        float boot;
        if (t + HORIZON <= TT) {
            boot = G16 * val[(t + HORIZON - 1) * BB + b];
        } else {
            boot = GP[TT - t] * val[(TT - 1) * BB + b];
        }
        out[t * BB + b] = S + boot;

        if (j < CH - 1) {
            // Slide window: add rm[t-1], drop rm[t+15].
            const float nv  = rew[(t - 1) * BB + b] * msk[(t - 1) * BB + b];
            const float rem = w[(t - 1) & (HORIZON - 1)];   // == rm[t+15] (16 = 0 mod 16)
            S = fmaf(GAMMA, S, nv) - G16 * rem;
            w[(t - 1) & (HORIZON - 1)] = nv;
        }
    }
}

extern "C" void kernel_launch(void* const* d_in, const int* in_sizes, int n_in,
                              void* d_out, int out_size)
{
    const float* rewards = (const float*)d_in[0];
    const float* values  = (const float*)d_in[1];
    const float* masks   = (const float*)d_in[2];
    float*       out     = (float*)d_out;

    dim3 block(256);
    dim3 grid(BB / 256, TT / CH);   // (16, 32) = 512 blocks, 4096 warps
    nstep_return_kernel<<<grid, block>>>(rewards, values, masks, out);
}

// round 5
// speedup vs baseline: 1.2531x; 1.2531x over previous
#include <cuda_runtime.h>

// N-step discounted return, T=1024, B=4096, horizon=16, gamma=0.99.
// g[t,b] = sum_{h=0..15, t+h<T} g^h * r[t+h,b]*m[t+h,b]
//        + g^{min(t+16,T)-t} * V[min(t+15,T-1), b]
//
// One thread per (column b, 16-row time chunk). The full 31-row rm window for
// the chunk is pre-loaded into a flat register array (front-batched LDGs, high
// MLP), then a backward sliding recurrence
//   S(t) = rm[t] + g*S(t+1) - g^16 * rm[t+16]
// produces the 16 outputs.

#define TT 1024
#define BB 4096
#define HORIZON 16
#define CH 16                       // time rows per thread
#define WIN (CH + HORIZON - 1)      // 31

constexpr float GAMMA = 0.99f;

__host__ __device__ constexpr float gpow(int n) {
    float x = 1.0f;
    for (int i = 0; i < n; ++i) x *= GAMMA;
    return x;
}

__device__ __constant__ float GP[17] = {
    gpow(0),  gpow(1),  gpow(2),  gpow(3),  gpow(4),  gpow(5),
    gpow(6),  gpow(7),  gpow(8),  gpow(9),  gpow(10), gpow(11),
    gpow(12), gpow(13), gpow(14), gpow(15), gpow(16)
};

__global__ __launch_bounds__(256)
void nstep_return_kernel(const float* __restrict__ rew,
                         const float* __restrict__ val,
                         const float* __restrict__ msk,
                         float* __restrict__ out)
{
    const int b  = blockIdx.x * 256 + threadIdx.x;   // column
    const int t0 = blockIdx.y * CH;                  // chunk start (TT % CH == 0)

    constexpr float G16 = gpow(16);

    // Pre-load rm[t0 .. t0+WIN-1] into registers. Compile-time indices, all
    // loads independent -> front-batched by ptxas for max MLP.
    float rm[WIN];
#pragma unroll
    for (int i = 0; i < WIN; ++i) {
        const int tt = t0 + i;
        float x = 0.0f;
        if (tt < TT) x = rew[tt * BB + b] * msk[tt * BB + b];
        rm[i] = x;
    }

    // S at t = t0 + CH - 1 (Horner over rm[CH-1 .. WIN-1]).
    float S = 0.0f;
#pragma unroll
    for (int i = WIN - 1; i >= CH - 1; --i) {
        S = fmaf(S, GAMMA, rm[i]);
    }

    // Backward over the chunk.
#pragma unroll
    for (int j = CH - 1; j >= 0; --j) {
        const int t = t0 + j;

        float boot;
        if (t + HORIZON <= TT) {
            boot = G16 * val[(t + HORIZON - 1) * BB + b];
        } else {
            boot = GP[TT - t] * val[(TT - 1) * BB + b];
        }
        out[t * BB + b] = S + boot;

        if (j > 0) {
            // Slide window down: add rm[t-1], drop rm[t+15].
            S = fmaf(GAMMA, S, rm[j - 1]) - G16 * rm[j + HORIZON - 1];
        }
    }
}

extern "C" void kernel_launch(void* const* d_in, const int* in_sizes, int n_in,
                              void* d_out, int out_size)
{
    const float* rewards = (const float*)d_in[0];
    const float* values  = (const float*)d_in[1];
    const float* masks   = (const float*)d_in[2];
    float*       out     = (float*)d_out;

    dim3 block(256);
    dim3 grid(BB / 256, TT / CH);   // (16, 64) = 1024 blocks
    nstep_return_kernel<<<grid, block>>>(rewards, values, masks, out);
}

// round 6
// speedup vs baseline: 1.3212x; 1.0544x over previous
#include <cuda_runtime.h>

// N-step discounted return, T=1024, B=4096, horizon=16, gamma=0.99.
// g[t,b] = sum_{h=0..15, t+h<T} g^h * r[t+h,b]*m[t+h,b]
//        + g^{min(t+16,T)-t} * V[min(t+15,T-1), b]
//
// Shared-memory time-tile version:
//  - block = 256 threads, owns 64 output rows x 64 columns
//  - phase 1: cooperative float4 loads of rew/mask for rows [t0, t0+80),
//             rm = rew*mask written to 20KB smem tile
//  - phase 2: thread = (col, 16-row chunk); backward sliding recurrence
//             S(t) = rm[t] + g*S(t+1) - g^16*rm[t+16] reading smem.

#define TT 1024
#define BB 4096
#define HORIZON 16
#define BCOL 64                     // columns per block
#define TROWS 64                    // output rows per block
#define WROWS (TROWS + HORIZON)     // 80 rows staged in smem (need 79, 80 for even split)

constexpr float GAMMA = 0.99f;

__host__ __device__ constexpr float gpow(int n) {
    float x = 1.0f;
    for (int i = 0; i < n; ++i) x *= GAMMA;
    return x;
}

__device__ __constant__ float GP[17] = {
    gpow(0),  gpow(1),  gpow(2),  gpow(3),  gpow(4),  gpow(5),
    gpow(6),  gpow(7),  gpow(8),  gpow(9),  gpow(10), gpow(11),
    gpow(12), gpow(13), gpow(14), gpow(15), gpow(16)
};

__global__ __launch_bounds__(256)
void nstep_return_kernel(const float* __restrict__ rew,
                         const float* __restrict__ val,
                         const float* __restrict__ msk,
                         float* __restrict__ out)
{
    __shared__ float rm[WROWS][BCOL];   // 80*64*4 = 20480 B

    const int tid   = threadIdx.x;
    const int bcol0 = blockIdx.x * BCOL;    // first column of this block
    const int t0    = blockIdx.y * TROWS;   // first output row of this block

    constexpr float G16 = gpow(16);

    // ---- Phase 1: stage rm = rew*mask for rows [t0, t0+WROWS) ----
    // 80 rows x 16 float4 = 1280 float4 slots; 256 threads x 5 iters.
#pragma unroll
    for (int it = 0; it < (WROWS * (BCOL / 4)) / 256; ++it) {
        const int i   = it * 256 + tid;
        const int r   = i >> 4;             // row within tile (/16 float4s per row)
        const int c4  = i & 15;             // float4 index within row
        const int tt  = t0 + r;

        float4 p = make_float4(0.f, 0.f, 0.f, 0.f);
        if (tt < TT) {
            const size_t off = (size_t)tt * BB + bcol0 + c4 * 4;
            const float4 rv = *reinterpret_cast<const float4*>(rew + off);
            const float4 mv = *reinterpret_cast<const float4*>(msk + off);
            p = make_float4(rv.x * mv.x, rv.y * mv.y, rv.z * mv.z, rv.w * mv.w);
        }
        *reinterpret_cast<float4*>(&rm[r][c4 * 4]) = p;
    }
    __syncthreads();

    // ---- Phase 2: sliding-window recurrence ----
    const int col   = tid & (BCOL - 1);        // 0..63  (warp lanes = consecutive cols)
    const int chunk = tid >> 6;                // 0..3
    const int tl0   = chunk * 16;              // local row base
    const int b     = bcol0 + col;

    // S at local row tl0+15: Horner over rm rows [tl0+15 .. tl0+30].
    float S = 0.0f;
#pragma unroll
    for (int i = HORIZON + 14; i >= 15; --i) {
        S = fmaf(S, GAMMA, rm[tl0 + i][col]);
    }

#pragma unroll
    for (int j = 15; j >= 0; --j) {
        const int t = t0 + tl0 + j;

        float boot;
        if (t + HORIZON <= TT) {
            boot = G16 * val[(size_t)(t + HORIZON - 1) * BB + b];
        } else {
            boot = GP[TT - t] * val[(size_t)(TT - 1) * BB + b];
        }
        out[(size_t)t * BB + b] = S + boot;

        if (j > 0) {
            // Slide window down: add rm[t-1], drop rm[t+15].
            S = fmaf(GAMMA, S, rm[tl0 + j - 1][col]) - G16 * rm[tl0 + j + 15][col];
        }
    }
}

extern "C" void kernel_launch(void* const* d_in, const int* in_sizes, int n_in,
                              void* d_out, int out_size)
{
    const float* rewards = (const float*)d_in[0];
    const float* values  = (const float*)d_in[1];
    const float* masks   = (const float*)d_in[2];
    float*       out     = (float*)d_out;

    dim3 block(256);
    dim3 grid(BB / BCOL, TT / TROWS);   // (64, 16) = 1024 blocks
    nstep_return_kernel<<<grid, block>>>(rewards, values, masks, out);
}